// round 11
// baseline (speedup 1.0000x reference)
#include <cuda_runtime.h>

#define BB 4
#define NT 1024
#define NA 8192
#define DD 128
#define SS 384
#define GA_TOT (BB*NA)     // 32768 atoms
#define BT_TOT (BB*NT)     // 4096 tokens
#define PAD_VALF (-1e9f)
#define QPITCH 132         // sh_q row pitch; 32*132 = 4224 = 128*33 (reuse as W_res^T)

// scratch (no allocs allowed)
__device__ float g_a2q[BT_TOT*DD];     // [B,T,128]  2 MB
__device__ float g_Wt[SS*DD];          // W_a2q transposed [s][d]

// ---------------------------------------------------------------------------
// k0: transpose W_a2q [128][384] -> g_Wt [384][128] (blocks 0..47)
//     + init out_res[bt][k] = b_res[k]               (all 96 blocks)
// ---------------------------------------------------------------------------
__global__ void k0_prep(const float* __restrict__ W,
                        const float* __restrict__ b_res,
                        float* __restrict__ out_res)
{
    __shared__ float t[32][33];
    __shared__ float br[33];
    const int tid = threadIdx.x;
    if (tid < 33) br[tid] = b_res[tid];

    if (blockIdx.x < 48) {
        const int x  = tid & 31;
        const int y8 = tid >> 5;
        const int td = (blockIdx.x & 3)  * 32;
        const int ts = (blockIdx.x >> 2) * 32;
#pragma unroll
        for (int j = 0; j < 32; j += 8)
            t[y8 + j][x] = W[(td + y8 + j)*SS + ts + x];
        __syncthreads();
#pragma unroll
        for (int j = 0; j < 32; j += 8)
            g_Wt[(ts + y8 + j)*DD + td + x] = t[x][y8 + j];
    } else {
        __syncthreads();
    }
    for (int i = blockIdx.x*256 + tid; i < BT_TOT*33; i += 96*256)
        out_res[i] = br[i % 33];
}

// ---------------------------------------------------------------------------
// k1: a_to_q = a[4096x384] @ Wt[384x128]
// tile: 16 tokens x 128 d, 256 threads, thread = 2 tok x 4 d. grid 256.
// ---------------------------------------------------------------------------
__global__ void __launch_bounds__(256) k1_gemm(const float* __restrict__ a)
{
    __shared__ float a_s[16][64];     // 4 KB
    __shared__ float w_s[64][128];    // 32 KB

    const int tid = threadIdx.x;
    const int bt0 = blockIdx.x * 16;
    const int dq  = tid & 31;         // d-quad (d = dq*4)
    const int tg  = tid >> 5;         // 0..7 -> tokens tg*2, tg*2+1

    float acc[2][4];
#pragma unroll
    for (int t = 0; t < 2; t++)
#pragma unroll
        for (int j = 0; j < 4; j++) acc[t][j] = 0.f;

    for (int sc = 0; sc < SS; sc += 64) {
        {
            int t = tid >> 4, c = tid & 15;
            *(float4*)&a_s[t][c*4] =
                *(const float4*)(a + (size_t)(bt0 + t)*SS + sc + c*4);
        }
        {
            const float4* wsrc = (const float4*)(g_Wt + sc*DD);
            float4* wdst = (float4*)w_s;
#pragma unroll
            for (int j = 0; j < 8; j++)
                wdst[tid + j*256] = wsrc[tid + j*256];
        }
        __syncthreads();

#pragma unroll
        for (int s = 0; s < 64; s += 4) {
            float4 w0 = *(float4*)&w_s[s+0][dq*4];
            float4 w1 = *(float4*)&w_s[s+1][dq*4];
            float4 w2 = *(float4*)&w_s[s+2][dq*4];
            float4 w3 = *(float4*)&w_s[s+3][dq*4];
#pragma unroll
            for (int t = 0; t < 2; t++) {
                float4 av = *(float4*)&a_s[tg*2 + t][s];
                acc[t][0] = fmaf(av.x, w0.x, fmaf(av.y, w1.x,
                            fmaf(av.z, w2.x, fmaf(av.w, w3.x, acc[t][0]))));
                acc[t][1] = fmaf(av.x, w0.y, fmaf(av.y, w1.y,
                            fmaf(av.z, w2.y, fmaf(av.w, w3.y, acc[t][1]))));
                acc[t][2] = fmaf(av.x, w0.z, fmaf(av.y, w1.z,
                            fmaf(av.z, w2.z, fmaf(av.w, w3.z, acc[t][2]))));
                acc[t][3] = fmaf(av.x, w0.w, fmaf(av.y, w1.w,
                            fmaf(av.z, w2.w, fmaf(av.w, w3.w, acc[t][3]))));
            }
        }
        __syncthreads();
    }
#pragma unroll
    for (int t = 0; t < 2; t++) {
        float4 v = make_float4(acc[t][0], acc[t][1], acc[t][2], acc[t][3]);
        *(float4*)(g_a2q + (size_t)(bt0 + tg*2 + t)*DD + dq*4) = v;
    }
}

// ---------------------------------------------------------------------------
// k2: fully fused per-atom stage (32 atoms / block, 256 threads, grid 1024)
//   qn = q + a_to_q[tok]                          (gather)
//   atom_type : logits -> lg; out_at emitted via inverse map
//   r_update  : LayerNorm(qn) @ W_pos^T
//   res head  : run-length Σqn per token-run -> 33 logits/run -> atomicAdd
//               into out_res (bias pre-initialized by k0)
// smem reuse: sh_wt (W_atom^T) -> run vectors; sh_q (q rows) -> W_res^T.
// ---------------------------------------------------------------------------
__global__ void __launch_bounds__(256) k2_atoms(
                         const float* __restrict__ q,
                         const int*   __restrict__ tok,
                         const float* __restrict__ W_atom,
                         const float* __restrict__ W_res,
                         const float* __restrict__ b_atom,
                         const int*   __restrict__ allowed,
                         const float* __restrict__ gamma,
                         const float* __restrict__ beta,
                         const float* __restrict__ W_pos,
                         float* __restrict__ out_r,
                         float* __restrict__ out_res,
                         float* __restrict__ out_at)
{
    __shared__ float sh_q[32*QPITCH];    // 16.9 KB: q rows; later W_res^T [d*33+k]
    __shared__ float sh_wt[DD*33];       // 16.9 KB: W_atom^T; later runs[32][128]
    __shared__ float lg[32*33];          // 4.2 KB atom logits [ia*33+k]
    __shared__ float sh_pos[3][DD];
    __shared__ float sh_g[DD], sh_b[DD];
    __shared__ float sh_batom[32];
    __shared__ int   sh_tok[32];
    __shared__ int   sh_allowed[32];
    __shared__ int   sh_inv[DD];         // col -> k (or -1)
    __shared__ int   run_tok[32];
    __shared__ int   run_cnt[2];

    const int tid   = threadIdx.x;
    const int atom0 = blockIdx.x * 32;
    const int b     = atom0 >> 13;          // atom0 / 8192

    if (tid < 32) {
        sh_tok[tid]     = tok[atom0 + tid];
        sh_batom[tid]   = b_atom[tid];
        sh_allowed[tid] = allowed[tid];
    }
    if (tid < DD) {
        sh_g[tid] = gamma[tid]; sh_b[tid] = beta[tid];
        sh_inv[tid] = -1;
    }
    for (int i = tid; i < 32*DD; i += 256)          // W_atom is [k][d]
        sh_wt[(i & 127)*33 + (i >> 7)] = W_atom[i]; // pitch 33: conflict-free
    for (int i = tid; i < 3*DD; i += 256)
        sh_pos[i >> 7][i & 127] = W_pos[i];
    __syncthreads();

    if (tid < 32) sh_inv[sh_allowed[tid]] = tid;    // visible after next sync

    // ---- gather qn (coalesced float4), pitch-132 rows ----
    for (int i = tid; i < 32*(DD/4); i += 256) {
        int ia = i >> 5, d4 = i & 31;
        int ga = atom0 + ia;
        int t  = sh_tok[ia];
        float4 qv = ((const float4*)q)[(size_t)ga*(DD/4) + d4];
        float4 av = ((const float4*)g_a2q)[(size_t)(b*NT + t)*(DD/4) + d4];
        *(float4*)&sh_q[ia*QPITCH + d4*4] =
            make_float4(qv.x+av.x, qv.y+av.y, qv.z+av.z, qv.w+av.w);
    }
    __syncthreads();

    // ---- atom-type head: thread (ig,k) owns logit k for 4 atoms ----
    const int k   = tid & 31;
    const int ig  = tid >> 5;          // warp id, 0..7
    const int ia0 = ig * 4;
    {
        float acc0 = sh_batom[k], acc1 = acc0, acc2 = acc0, acc3 = acc0;
#pragma unroll 8
        for (int d = 0; d < DD; d += 4) {
            float w0 = sh_wt[(d+0)*33 + k], w1 = sh_wt[(d+1)*33 + k];
            float w2 = sh_wt[(d+2)*33 + k], w3 = sh_wt[(d+3)*33 + k];
            float4 q0 = *(const float4*)&sh_q[(ia0+0)*QPITCH + d];
            float4 q1 = *(const float4*)&sh_q[(ia0+1)*QPITCH + d];
            float4 q2 = *(const float4*)&sh_q[(ia0+2)*QPITCH + d];
            float4 q3 = *(const float4*)&sh_q[(ia0+3)*QPITCH + d];
            acc0 += q0.x*w0 + q0.y*w1 + q0.z*w2 + q0.w*w3;
            acc1 += q1.x*w0 + q1.y*w1 + q1.z*w2 + q1.w*w3;
            acc2 += q2.x*w0 + q2.y*w1 + q2.z*w2 + q2.w*w3;
            acc3 += q3.x*w0 + q3.y*w1 + q3.z*w2 + q3.w*w3;
        }
        lg[(ia0+0)*33 + k] = acc0;
        lg[(ia0+1)*33 + k] = acc1;
        lg[(ia0+2)*33 + k] = acc2;
        lg[(ia0+3)*33 + k] = acc3;
    }
    __syncthreads();   // atom head done: lg valid, sh_wt free

    // ---- out_at: direct float4 emit via inverse map ----
    for (int i = tid; i < 32*(DD/4); i += 256) {
        int ia = i >> 5, d4 = i & 31;
        int c0 = d4 * 4;
        int k0 = sh_inv[c0+0], k1 = sh_inv[c0+1];
        int k2 = sh_inv[c0+2], k3 = sh_inv[c0+3];
        float4 v;
        v.x = (k0 >= 0) ? lg[ia*33 + k0] : PAD_VALF;
        v.y = (k1 >= 0) ? lg[ia*33 + k1] : PAD_VALF;
        v.z = (k2 >= 0) ? lg[ia*33 + k2] : PAD_VALF;
        v.w = (k3 >= 0) ? lg[ia*33 + k3] : PAD_VALF;
        ((float4*)out_at)[(size_t)(atom0 + ia)*(DD/4) + d4] = v;
    }

    // ---- run-length extraction: Σqn per token-run -> sh_wt[run][128] ----
    {
        int d    = tid & 127;
        int half = tid >> 7;
        int i0   = half * 16;
        int rb   = half * 16;          // run slot base
        int r    = 0;
        int cur  = sh_tok[i0];
        float run = 0.f;
#pragma unroll
        for (int i = 0; i < 16; i++) {
            int t = sh_tok[i0 + i];
            if (t != cur) {
                sh_wt[(rb + r)*DD + d] = run;
                if (d == 0) run_tok[rb + r] = cur;
                r++; run = 0.f; cur = t;
            }
            run += sh_q[(i0 + i)*QPITCH + d];
        }
        sh_wt[(rb + r)*DD + d] = run;
        if (d == 0) { run_tok[rb + r] = cur; run_cnt[half] = r + 1; }
    }

    // ---- LayerNorm + pos head: warp ig handles atoms ia0..ia0+3 ----
    {
        const int lane  = k;
        const int dbase = lane * 4;
        for (int r = 0; r < 4; r++) {
            int ia = ia0 + r;
            float4 v = *(const float4*)&sh_q[ia*QPITCH + dbase];
            float s = v.x + v.y + v.z + v.w;
#pragma unroll
            for (int o = 16; o > 0; o >>= 1) s += __shfl_xor_sync(0xffffffffu, s, o);
            float mu = s * (1.f/128.f);
            float d0 = v.x-mu, d1 = v.y-mu, d2 = v.z-mu, d3 = v.w-mu;
            float sq = d0*d0 + d1*d1 + d2*d2 + d3*d3;
#pragma unroll
            for (int o = 16; o > 0; o >>= 1) sq += __shfl_xor_sync(0xffffffffu, sq, o);
            float inv = rsqrtf(sq * (1.f/128.f) + 1e-5f);
            float n0 = d0*inv*sh_g[dbase+0] + sh_b[dbase+0];
            float n1 = d1*inv*sh_g[dbase+1] + sh_b[dbase+1];
            float n2 = d2*inv*sh_g[dbase+2] + sh_b[dbase+2];
            float n3 = d3*inv*sh_g[dbase+3] + sh_b[dbase+3];
            float p0 = n0*sh_pos[0][dbase+0] + n1*sh_pos[0][dbase+1]
                     + n2*sh_pos[0][dbase+2] + n3*sh_pos[0][dbase+3];
            float p1 = n0*sh_pos[1][dbase+0] + n1*sh_pos[1][dbase+1]
                     + n2*sh_pos[1][dbase+2] + n3*sh_pos[1][dbase+3];
            float p2 = n0*sh_pos[2][dbase+0] + n1*sh_pos[2][dbase+1]
                     + n2*sh_pos[2][dbase+2] + n3*sh_pos[2][dbase+3];
#pragma unroll
            for (int o = 16; o > 0; o >>= 1) {
                p0 += __shfl_xor_sync(0xffffffffu, p0, o);
                p1 += __shfl_xor_sync(0xffffffffu, p1, o);
                p2 += __shfl_xor_sync(0xffffffffu, p2, o);
            }
            if (lane == 0) {
                size_t ro = (size_t)(atom0 + ia) * 3;
                out_r[ro+0] = p0; out_r[ro+1] = p1; out_r[ro+2] = p2;
            }
        }
    }
    __syncthreads();   // runs visible; all sh_q reads done

    // ---- restage W_res^T into sh_q region: [d*33 + kk] ----
    for (int i = tid; i < 33*DD; i += 256)          // i = kk*128 + d
        sh_q[(i & 127)*33 + (i >> 7)] = W_res[i];
    __syncthreads();

    // ---- res head per run: warp ig owns run slots ig*4..ig*4+3 ----
    {
        const int s0   = ig * 4;
        const int half = s0 >> 4;
        const int idx0 = s0 & 15;
        const int cnt  = run_cnt[half];
        if (idx0 < cnt) {                  // warp-uniform skip
            const float* runs = sh_wt;
            float r0 = 0.f, r1 = 0.f, r2 = 0.f, r3 = 0.f;
#pragma unroll 8
            for (int d = 0; d < DD; d += 4) {
                float w0 = sh_q[(d+0)*33 + k], w1 = sh_q[(d+1)*33 + k];
                float w2 = sh_q[(d+2)*33 + k], w3 = sh_q[(d+3)*33 + k];
                float4 v0 = *(const float4*)&runs[(s0+0)*DD + d];
                float4 v1 = *(const float4*)&runs[(s0+1)*DD + d];
                float4 v2 = *(const float4*)&runs[(s0+2)*DD + d];
                float4 v3 = *(const float4*)&runs[(s0+3)*DD + d];
                r0 += v0.x*w0 + v0.y*w1 + v0.z*w2 + v0.w*w3;
                r1 += v1.x*w0 + v1.y*w1 + v1.z*w2 + v1.w*w3;
                r2 += v2.x*w0 + v2.y*w1 + v2.z*w2 + v2.w*w3;
                r3 += v3.x*w0 + v3.y*w1 + v3.z*w2 + v3.w*w3;
            }
            float rr[4] = {r0, r1, r2, r3};
#pragma unroll
            for (int j = 0; j < 4; j++)
                if (idx0 + j < cnt)
                    atomicAdd(&out_res[(size_t)(b*NT + run_tok[s0+j])*33 + k],
                              rr[j]);
            // k = 32: lane-parallel partial dot + shuffle reduce per run
            const int dbase = k * 4;
            float w0 = sh_q[(dbase+0)*33 + 32];
            float w1 = sh_q[(dbase+1)*33 + 32];
            float w2 = sh_q[(dbase+2)*33 + 32];
            float w3 = sh_q[(dbase+3)*33 + 32];
#pragma unroll
            for (int j = 0; j < 4; j++) {
                if (idx0 + j < cnt) {
                    float4 v = *(const float4*)&runs[(s0+j)*DD + dbase];
                    float s = v.x*w0 + v.y*w1 + v.z*w2 + v.w*w3;
#pragma unroll
                    for (int o = 16; o > 0; o >>= 1)
                        s += __shfl_xor_sync(0xffffffffu, s, o);
                    if (k == 0)
                        atomicAdd(&out_res[(size_t)(b*NT + run_tok[s0+j])*33 + 32], s);
                }
            }
        }
    }
}

// ---------------------------------------------------------------------------
extern "C" void kernel_launch(void* const* d_in, const int* in_sizes, int n_in,
                              void* d_out, int out_size)
{
    const float* a      = (const float*)d_in[0];
    const float* q      = (const float*)d_in[1];
    // d_in[2] = c            (unused by reference)
    const int*   tok    = (const int*)  d_in[3];
    // d_in[4] = atom_to_token one-hot (replaced by gather via tok)
    // d_in[5] = atom_pad_mask (all ones by construction)
    const float* W_a2q  = (const float*)d_in[6];
    const float* gamma  = (const float*)d_in[7];
    const float* beta   = (const float*)d_in[8];
    const float* W_pos  = (const float*)d_in[9];
    const float* W_res  = (const float*)d_in[10];
    const float* b_res  = (const float*)d_in[11];
    const float* W_atom = (const float*)d_in[12];
    const float* b_atom = (const float*)d_in[13];
    const int*   allowed= (const int*)  d_in[14];

    float* out     = (float*)d_out;
    float* out_r   = out;                                   // [B,NA,3]
    float* out_res = out + (size_t)BB*NA*3;                 // [B,NT,33]
    float* out_at  = out_res + (size_t)BB*NT*33;            // [B,NA,128]

    k0_prep <<<96, 256>>>(W_a2q, b_res, out_res);
    k1_gemm <<<BT_TOT/16, 256>>>(a);
    k2_atoms<<<GA_TOT/32, 256>>>(q, tok, W_atom, W_res, b_atom, allowed,
                                 gamma, beta, W_pos,
                                 out_r, out_res, out_at);
}

// round 12
// speedup vs baseline: 1.0478x; 1.0478x over previous
#include <cuda_runtime.h>

#define BB 4
#define NT 1024
#define NA 8192
#define DD 128
#define SS 384
#define GA_TOT (BB*NA)     // 32768 atoms
#define BT_TOT (BB*NT)     // 4096 tokens
#define PAD_VALF (-1e9f)

// scratch (no allocs allowed)
__device__ float g_a2q[BT_TOT*DD];     // [B,T,128]  2 MB
__device__ float g_sfeat[BT_TOT*DD];   // [B,T,128]  2 MB
__device__ float g_Wt[SS*DD];          // W_a2q transposed [s][d]

// f32x2 packed helpers (sm_103a FFMA2 path)
__device__ __forceinline__ unsigned long long dup_f32x2(float x) {
    unsigned long long r;
    unsigned xi = __float_as_uint(x);
    asm("mov.b64 %0, {%1, %1};" : "=l"(r) : "r"(xi));
    return r;
}
__device__ __forceinline__ void fma_f32x2(unsigned long long& acc,
                                          unsigned long long a,
                                          unsigned long long b) {
    asm("fma.rn.f32x2 %0, %1, %2, %0;" : "+l"(acc) : "l"(a), "l"(b));
}
__device__ __forceinline__ float2 unpack_f32x2(unsigned long long v) {
    unsigned lo, hi;
    asm("mov.b64 {%0, %1}, %2;" : "=r"(lo), "=r"(hi) : "l"(v));
    return make_float2(__uint_as_float(lo), __uint_as_float(hi));
}

// ---------------------------------------------------------------------------
// k0: transpose W_a2q [128][384] -> g_Wt [384][128]
// grid 48 blocks x 256 threads (4 d-tiles x 12 s-tiles of 32x32)
// ---------------------------------------------------------------------------
__global__ void k0_prep(const float* __restrict__ W)
{
    __shared__ float t[32][33];
    const int tid = threadIdx.x;
    const int x  = tid & 31;
    const int y8 = tid >> 5;                  // 0..7
    const int td = (blockIdx.x & 3)  * 32;    // d tile
    const int ts = (blockIdx.x >> 2) * 32;    // s tile
#pragma unroll
    for (int j = 0; j < 32; j += 8)
        t[y8 + j][x] = W[(td + y8 + j)*SS + ts + x];
    __syncthreads();
#pragma unroll
    for (int j = 0; j < 32; j += 8)
        g_Wt[(ts + y8 + j)*DD + td + x] = t[x][y8 + j];
}

// ---------------------------------------------------------------------------
// k1: a_to_q = a[4096x384] @ Wt[384x128]   (+ zero g_sfeat in prologue)
// tile: 16 tokens x 128 d, 256 threads, thread = 2 tok x 4 d. grid 256.
// Inner loop uses packed fma.rn.f32x2 (FFMA2): 4 FFMA2 per s covering
// 2 tokens x 4 d; w pairs loaded directly as ulonglong2 from smem.
// ---------------------------------------------------------------------------
__global__ void __launch_bounds__(256) k1_gemm(const float* __restrict__ a)
{
    // zero g_sfeat: 131072 float4 over 65536 threads -> 2 each
    {
        int gz = blockIdx.x * 256 + threadIdx.x;
        float4 z = make_float4(0.f, 0.f, 0.f, 0.f);
        ((float4*)g_sfeat)[gz]         = z;
        ((float4*)g_sfeat)[gz + 65536] = z;
    }

    __shared__ float a_s[16][64];     // 4 KB
    __shared__ float w_s[64][128];    // 32 KB

    const int tid = threadIdx.x;
    const int bt0 = blockIdx.x * 16;
    const int dq  = tid & 31;         // d-quad (d = dq*4)
    const int tg  = tid >> 5;         // 0..7 -> tokens tg*2, tg*2+1

    // acc[t][p]: token tg*2+t, d-pair dq*4 + 2p + {0,1}; fp32 +0 = 0 bits
    unsigned long long acc[2][2] = {{0ull, 0ull}, {0ull, 0ull}};

    for (int sc = 0; sc < SS; sc += 64) {
        {
            int t = tid >> 4, c = tid & 15;
            *(float4*)&a_s[t][c*4] =
                *(const float4*)(a + (size_t)(bt0 + t)*SS + sc + c*4);
        }
        {
            const float4* wsrc = (const float4*)(g_Wt + sc*DD);
            float4* wdst = (float4*)w_s;
#pragma unroll
            for (int j = 0; j < 8; j++)
                wdst[tid + j*256] = wsrc[tid + j*256];
        }
        __syncthreads();

#pragma unroll 8
        for (int s = 0; s < 64; s++) {
            ulonglong2 w2 = *(const ulonglong2*)&w_s[s][dq*4];
            unsigned long long a0 = dup_f32x2(a_s[tg*2 + 0][s]);
            unsigned long long a1 = dup_f32x2(a_s[tg*2 + 1][s]);
            fma_f32x2(acc[0][0], a0, w2.x);
            fma_f32x2(acc[0][1], a0, w2.y);
            fma_f32x2(acc[1][0], a1, w2.x);
            fma_f32x2(acc[1][1], a1, w2.y);
        }
        __syncthreads();
    }
#pragma unroll
    for (int t = 0; t < 2; t++) {
        float2 p0 = unpack_f32x2(acc[t][0]);
        float2 p1 = unpack_f32x2(acc[t][1]);
        float4 v = make_float4(p0.x, p0.y, p1.x, p1.y);
        *(float4*)(g_a2q + (size_t)(bt0 + tg*2 + t)*DD + dq*4) = v;
    }
}

// ---------------------------------------------------------------------------
// k2: per-atom fused stage (32 atoms / block, 256 threads, grid 1024)
//   qn = q + a_to_q[tok]            (gather)
//   s_feat[tok] += qn               (run-length aggregated atomics)
//   atom_type: logits -> lg smem; out_at emitted directly via inverse map
//   r_update : LayerNorm(qn) @ W_pos^T
// ---------------------------------------------------------------------------
__global__ void __launch_bounds__(256) k2_atoms(
                         const float* __restrict__ q,
                         const int*   __restrict__ tok,
                         const float* __restrict__ W_atom,
                         const float* __restrict__ b_atom,
                         const int*   __restrict__ allowed,
                         const float* __restrict__ gamma,
                         const float* __restrict__ beta,
                         const float* __restrict__ W_pos,
                         float* __restrict__ out_r,
                         float* __restrict__ out_at)
{
    __shared__ float sh_q[32][DD];       // 16 KB
    __shared__ float sh_wt[DD*33];       // 16.9 KB: W_atom^T [d*33+k]
    __shared__ float lg[32*33];          // 4.2 KB atom logits [ia*33+k]
    __shared__ float sh_pos[3][DD];
    __shared__ float sh_g[DD], sh_b[DD];
    __shared__ float sh_batom[32];
    __shared__ int   sh_tok[32];
    __shared__ int   sh_allowed[32];
    __shared__ int   sh_inv[DD];         // col -> k (or -1)

    const int tid   = threadIdx.x;
    const int atom0 = blockIdx.x * 32;
    const int b     = atom0 >> 13;          // atom0 / 8192

    if (tid < 32) {
        sh_tok[tid]     = tok[atom0 + tid];
        sh_batom[tid]   = b_atom[tid];
        sh_allowed[tid] = allowed[tid];
    }
    if (tid < DD) {
        sh_g[tid] = gamma[tid]; sh_b[tid] = beta[tid];
        sh_inv[tid] = -1;
    }
    for (int i = tid; i < 32*DD; i += 256)          // W_atom is [k][d]
        sh_wt[(i & 127)*33 + (i >> 7)] = W_atom[i]; // pitch 33: conflict-free
    for (int i = tid; i < 3*DD; i += 256)
        sh_pos[i >> 7][i & 127] = W_pos[i];
    __syncthreads();

    if (tid < 32) sh_inv[sh_allowed[tid]] = tid;    // visible after next sync

    // ---- gather (coalesced float4) ----
    for (int i = tid; i < 32*(DD/4); i += 256) {
        int ia = i >> 5, d4 = i & 31;
        int ga = atom0 + ia;
        int t  = sh_tok[ia];
        float4 qv = ((const float4*)q)[(size_t)ga*(DD/4) + d4];
        float4 av = ((const float4*)g_a2q)[(size_t)(b*NT + t)*(DD/4) + d4];
        *(float4*)&sh_q[ia][d4*4] =
            make_float4(qv.x+av.x, qv.y+av.y, qv.z+av.z, qv.w+av.w);
    }
    __syncthreads();

    // ---- scatter-add, run-length aggregated (tok sorted => ~4 runs/block) ----
    {
        int d    = tid & 127;
        int i0   = (tid >> 7) * 16;
        int cur  = sh_tok[i0];
        float run = 0.f;
#pragma unroll
        for (int i = 0; i < 16; i++) {
            int t = sh_tok[i0 + i];
            if (t != cur) {
                atomicAdd(&g_sfeat[(size_t)(b*NT + cur)*DD + d], run);
                run = 0.f; cur = t;
            }
            run += sh_q[i0 + i][d];
        }
        atomicAdd(&g_sfeat[(size_t)(b*NT + cur)*DD + d], run);
    }

    // ---- atom-type head: thread (ig,k) owns logit k for 4 atoms ----
    const int k   = tid & 31;
    const int ig  = tid >> 5;          // warp id, 0..7
    const int ia0 = ig * 4;
    float acc0 = sh_batom[k], acc1 = acc0, acc2 = acc0, acc3 = acc0;
#pragma unroll 8
    for (int d = 0; d < DD; d += 4) {
        float w0 = sh_wt[(d+0)*33 + k], w1 = sh_wt[(d+1)*33 + k];
        float w2 = sh_wt[(d+2)*33 + k], w3 = sh_wt[(d+3)*33 + k];
        float4 q0 = *(const float4*)&sh_q[ia0+0][d];
        float4 q1 = *(const float4*)&sh_q[ia0+1][d];
        float4 q2 = *(const float4*)&sh_q[ia0+2][d];
        float4 q3 = *(const float4*)&sh_q[ia0+3][d];
        acc0 += q0.x*w0 + q0.y*w1 + q0.z*w2 + q0.w*w3;
        acc1 += q1.x*w0 + q1.y*w1 + q1.z*w2 + q1.w*w3;
        acc2 += q2.x*w0 + q2.y*w1 + q2.z*w2 + q2.w*w3;
        acc3 += q3.x*w0 + q3.y*w1 + q3.z*w2 + q3.w*w3;
    }
    lg[(ia0+0)*33 + k] = acc0;
    lg[(ia0+1)*33 + k] = acc1;
    lg[(ia0+2)*33 + k] = acc2;
    lg[(ia0+3)*33 + k] = acc3;
    __syncthreads();

    // ---- out_at: direct float4 emit via inverse map ----
    for (int i = tid; i < 32*(DD/4); i += 256) {
        int ia = i >> 5, d4 = i & 31;
        int c0 = d4 * 4;
        int k0 = sh_inv[c0+0], k1 = sh_inv[c0+1];
        int k2 = sh_inv[c0+2], k3 = sh_inv[c0+3];
        float4 v;
        v.x = (k0 >= 0) ? lg[ia*33 + k0] : PAD_VALF;
        v.y = (k1 >= 0) ? lg[ia*33 + k1] : PAD_VALF;
        v.z = (k2 >= 0) ? lg[ia*33 + k2] : PAD_VALF;
        v.w = (k3 >= 0) ? lg[ia*33 + k3] : PAD_VALF;
        ((float4*)out_at)[(size_t)(atom0 + ia)*(DD/4) + d4] = v;
    }

    // ---- LayerNorm + pos head: warp ig handles atoms ia0..ia0+3 ----
    const int lane  = k;
    const int dbase = lane * 4;
    for (int r = 0; r < 4; r++) {
        int ia = ia0 + r;
        float4 v = *(const float4*)&sh_q[ia][dbase];
        float s = v.x + v.y + v.z + v.w;
#pragma unroll
        for (int o = 16; o > 0; o >>= 1) s += __shfl_xor_sync(0xffffffffu, s, o);
        float mu = s * (1.f/128.f);
        float d0 = v.x-mu, d1 = v.y-mu, d2 = v.z-mu, d3 = v.w-mu;
        float sq = d0*d0 + d1*d1 + d2*d2 + d3*d3;
#pragma unroll
        for (int o = 16; o > 0; o >>= 1) sq += __shfl_xor_sync(0xffffffffu, sq, o);
        float inv = rsqrtf(sq * (1.f/128.f) + 1e-5f);
        float n0 = d0*inv*sh_g[dbase+0] + sh_b[dbase+0];
        float n1 = d1*inv*sh_g[dbase+1] + sh_b[dbase+1];
        float n2 = d2*inv*sh_g[dbase+2] + sh_b[dbase+2];
        float n3 = d3*inv*sh_g[dbase+3] + sh_b[dbase+3];
        float p0 = n0*sh_pos[0][dbase+0] + n1*sh_pos[0][dbase+1]
                 + n2*sh_pos[0][dbase+2] + n3*sh_pos[0][dbase+3];
        float p1 = n0*sh_pos[1][dbase+0] + n1*sh_pos[1][dbase+1]
                 + n2*sh_pos[1][dbase+2] + n3*sh_pos[1][dbase+3];
        float p2 = n0*sh_pos[2][dbase+0] + n1*sh_pos[2][dbase+1]
                 + n2*sh_pos[2][dbase+2] + n3*sh_pos[2][dbase+3];
#pragma unroll
        for (int o = 16; o > 0; o >>= 1) {
            p0 += __shfl_xor_sync(0xffffffffu, p0, o);
            p1 += __shfl_xor_sync(0xffffffffu, p1, o);
            p2 += __shfl_xor_sync(0xffffffffu, p2, o);
        }
        if (lane == 0) {
            size_t ro = (size_t)(atom0 + ia) * 3;
            out_r[ro+0] = p0; out_r[ro+1] = p1; out_r[ro+2] = p2;
        }
    }
}

// ---------------------------------------------------------------------------
// k3: res_type[bt,k] = s_feat[bt,:] . W_res[k,:] + b_res[k]
// 256 blocks x 256 threads; 16 tokens/block; warp = 2 tokens, lane = k.
// W_res staged [k][132] -> per-lane LDS.128, conflict-free per quarter-warp.
// ---------------------------------------------------------------------------
__global__ void __launch_bounds__(256) k3_res(const float* __restrict__ W_res,
                                              const float* __restrict__ b_res,
                                              float* __restrict__ out_res)
{
    __shared__ float shW[33*132];    // 17.4 KB: [k][132]
    __shared__ float shF[16*DD];     // 8 KB

    const int tid = threadIdx.x;
    const int bt0 = blockIdx.x * 16;

    for (int i = tid; i < 33*DD; i += 256)          // i = k*128 + d
        shW[(i >> 7)*132 + (i & 127)] = W_res[i];
    {
        const float4* src = (const float4*)(g_sfeat + (size_t)bt0*DD);
        ((float4*)shF)[tid]       = src[tid];
        ((float4*)shF)[tid + 256] = src[tid + 256];
    }
    __syncthreads();

    const int lane = tid & 31;                      // k
    const int w    = tid >> 5;                      // 0..7
    const int t0   = w * 2;
    const float* f0p = &shF[t0*DD];
    const float* f1p = &shF[(t0+1)*DD];

    float acc0 = b_res[lane];
    float acc1 = acc0;
#pragma unroll 16
    for (int d = 0; d < DD; d += 4) {
        float4 wv = *(const float4*)&shW[lane*132 + d];
        float4 f0 = *(const float4*)(f0p + d);
        float4 f1 = *(const float4*)(f1p + d);
        acc0 = fmaf(f0.x, wv.x, fmaf(f0.y, wv.y,
               fmaf(f0.z, wv.z, fmaf(f0.w, wv.w, acc0))));
        acc1 = fmaf(f1.x, wv.x, fmaf(f1.y, wv.y,
               fmaf(f1.z, wv.z, fmaf(f1.w, wv.w, acc1))));
    }
    out_res[(size_t)(bt0 + t0)*33 + lane]     = acc0;
    out_res[(size_t)(bt0 + t0 + 1)*33 + lane] = acc1;

    // k = 32: lane-parallel partial dots + shuffle reduce (both tokens)
    {
        const int dbase = lane * 4;
        float4 wv = *(const float4*)&shW[32*132 + dbase];
        float4 a0 = *(const float4*)(f0p + dbase);
        float4 a1 = *(const float4*)(f1p + dbase);
        float s0 = a0.x*wv.x + a0.y*wv.y + a0.z*wv.z + a0.w*wv.w;
        float s1 = a1.x*wv.x + a1.y*wv.y + a1.z*wv.z + a1.w*wv.w;
#pragma unroll
        for (int o = 16; o > 0; o >>= 1) {
            s0 += __shfl_xor_sync(0xffffffffu, s0, o);
            s1 += __shfl_xor_sync(0xffffffffu, s1, o);
        }
        if (lane == 0) {
            float b32 = b_res[32];
            out_res[(size_t)(bt0 + t0)*33 + 32]     = s0 + b32;
            out_res[(size_t)(bt0 + t0 + 1)*33 + 32] = s1 + b32;
        }
    }
}

// ---------------------------------------------------------------------------
extern "C" void kernel_launch(void* const* d_in, const int* in_sizes, int n_in,
                              void* d_out, int out_size)
{
    const float* a      = (const float*)d_in[0];
    const float* q      = (const float*)d_in[1];
    // d_in[2] = c            (unused by reference)
    const int*   tok    = (const int*)  d_in[3];
    // d_in[4] = atom_to_token one-hot (replaced by gather via tok)
    // d_in[5] = atom_pad_mask (all ones by construction)
    const float* W_a2q  = (const float*)d_in[6];
    const float* gamma  = (const float*)d_in[7];
    const float* beta   = (const float*)d_in[8];
    const float* W_pos  = (const float*)d_in[9];
    const float* W_res  = (const float*)d_in[10];
    const float* b_res  = (const float*)d_in[11];
    const float* W_atom = (const float*)d_in[12];
    const float* b_atom = (const float*)d_in[13];
    const int*   allowed= (const int*)  d_in[14];

    float* out     = (float*)d_out;
    float* out_r   = out;                                   // [B,NA,3]
    float* out_res = out + (size_t)BB*NA*3;                 // [B,NT,33]
    float* out_at  = out_res + (size_t)BB*NT*33;            // [B,NA,128]

    k0_prep <<<48, 256>>>(W_a2q);
    k1_gemm <<<BT_TOT/16, 256>>>(a);
    k2_atoms<<<GA_TOT/32, 256>>>(q, tok, W_atom, b_atom, allowed,
                                 gamma, beta, W_pos, out_r, out_at);
    k3_res  <<<BT_TOT/16, 256>>>(W_res, b_res, out_res);
}

// round 13
// speedup vs baseline: 1.0608x; 1.0124x over previous
#include <cuda_runtime.h>

#define BB 4
#define NT 1024
#define NA 8192
#define DD 128
#define SS 384
#define GA_TOT (BB*NA)     // 32768 atoms
#define BT_TOT (BB*NT)     // 4096 tokens
#define PAD_VALF (-1e9f)
#define WPITCH 68          // k1 w_s row pitch (floats)

// scratch (no allocs allowed)
__device__ float g_a2q[BT_TOT*DD];     // [B,T,128]  2 MB
__device__ float g_sfeat[BT_TOT*DD];   // [B,T,128]  2 MB

// f32x2 packed helpers (sm_103a FFMA2 path)
__device__ __forceinline__ void fma_f32x2(unsigned long long& acc,
                                          unsigned long long a,
                                          unsigned long long b) {
    asm("fma.rn.f32x2 %0, %1, %2, %0;" : "+l"(acc) : "l"(a), "l"(b));
}
__device__ __forceinline__ float2 unpack_f32x2(unsigned long long v) {
    unsigned lo, hi;
    asm("mov.b64 {%0, %1}, %2;" : "=r"(lo), "=r"(hi) : "l"(v));
    return make_float2(__uint_as_float(lo), __uint_as_float(hi));
}

// ---------------------------------------------------------------------------
// k1: a_to_q = a[4096x384] @ W^T (W read directly, no pre-transpose)
// tile: 16 tokens x 128 d, 256 threads; thread = 2 tok x 4 d (d = dq+32j).
// w_s[128][WPITCH] staged straight from W rows; FFMA2 packed along s.
// Prologue zeroes g_sfeat. grid 256.
// ---------------------------------------------------------------------------
__global__ void __launch_bounds__(256) k1_gemm(const float* __restrict__ a,
                                               const float* __restrict__ W)
{
    // zero g_sfeat: 131072 float4 over 65536 threads -> 2 each
    {
        int gz = blockIdx.x * 256 + threadIdx.x;
        float4 z = make_float4(0.f, 0.f, 0.f, 0.f);
        ((float4*)g_sfeat)[gz]         = z;
        ((float4*)g_sfeat)[gz + 65536] = z;
    }

    __shared__ __align__(16) float a_s[16][64];        // 4 KB
    __shared__ __align__(16) float w_s[DD*WPITCH];     // 34.8 KB

    const int tid = threadIdx.x;
    const int bt0 = blockIdx.x * 16;
    const int dq  = tid & 31;         // d base lane
    const int tg  = tid >> 5;         // 0..7 -> tokens tg*2, tg*2+1

    unsigned long long acc[2][4] = {{0ull,0ull,0ull,0ull},
                                    {0ull,0ull,0ull,0ull}};

    for (int sc = 0; sc < SS; sc += 64) {
        // stage a tile: 16 tokens x 16 float4 (coalesced)
        {
            int t = tid >> 4, c = tid & 15;
            *(float4*)&a_s[t][c*4] =
                *(const float4*)(a + (size_t)(bt0 + t)*SS + sc + c*4);
        }
        // stage w: w_s[d][s] = W[d][sc+s]; 2048 float4, 8 per thread
#pragma unroll
        for (int kk = 0; kk < 8; kk++) {
            int idx = tid + kk*256;
            int d = idx >> 4, s4 = idx & 15;
            *(float4*)&w_s[d*WPITCH + s4*4] =
                *(const float4*)(W + (size_t)d*SS + sc + s4*4);
        }
        __syncthreads();

#pragma unroll 4
        for (int s = 0; s < 64; s += 4) {
            ulonglong2 a0u = *(const ulonglong2*)&a_s[tg*2 + 0][s];  // broadcast
            ulonglong2 a1u = *(const ulonglong2*)&a_s[tg*2 + 1][s];
#pragma unroll
            for (int j = 0; j < 4; j++) {
                ulonglong2 wu =
                    *(const ulonglong2*)&w_s[(dq + 32*j)*WPITCH + s];
                fma_f32x2(acc[0][j], a0u.x, wu.x);
                fma_f32x2(acc[0][j], a0u.y, wu.y);
                fma_f32x2(acc[1][j], a1u.x, wu.x);
                fma_f32x2(acc[1][j], a1u.y, wu.y);
            }
        }
        __syncthreads();
    }
#pragma unroll
    for (int t = 0; t < 2; t++) {
        size_t rbase = (size_t)(bt0 + tg*2 + t)*DD;
#pragma unroll
        for (int j = 0; j < 4; j++) {
            float2 p = unpack_f32x2(acc[t][j]);
            g_a2q[rbase + dq + 32*j] = p.x + p.y;   // warp-coalesced STG.32
        }
    }
}

// ---------------------------------------------------------------------------
// k2: per-atom fused stage (32 atoms / block, 256 threads, grid 1024)
//   qn = q + a_to_q[tok]            (gather)
//   s_feat[tok] += qn               (run-length aggregated atomics)
//   atom_type: FFMA2 head (W_atom d-pair packed) -> lg; out_at via inverse map
//   r_update : LayerNorm(qn) @ W_pos^T
// ---------------------------------------------------------------------------
__global__ void __launch_bounds__(256) k2_atoms(
                         const float* __restrict__ q,
                         const int*   __restrict__ tok,
                         const float* __restrict__ W_atom,
                         const float* __restrict__ b_atom,
                         const int*   __restrict__ allowed,
                         const float* __restrict__ gamma,
                         const float* __restrict__ beta,
                         const float* __restrict__ W_pos,
                         float* __restrict__ out_r,
                         float* __restrict__ out_at)
{
    __shared__ __align__(16) float sh_q[32][DD];   // 16 KB
    __shared__ __align__(16) float sh_wt[DD*33];   // 16.9 KB: u64 pairs [p*33+k]
    __shared__ float lg[32*33];          // 4.2 KB atom logits [ia*33+k]
    __shared__ float sh_pos[3][DD];
    __shared__ float sh_g[DD], sh_b[DD];
    __shared__ float sh_batom[32];
    __shared__ int   sh_tok[32];
    __shared__ int   sh_allowed[32];
    __shared__ int   sh_inv[DD];         // col -> k (or -1)

    const int tid   = threadIdx.x;
    const int atom0 = blockIdx.x * 32;
    const int b     = atom0 >> 13;          // atom0 / 8192

    if (tid < 32) {
        sh_tok[tid]     = tok[atom0 + tid];
        sh_batom[tid]   = b_atom[tid];
        sh_allowed[tid] = allowed[tid];
    }
    if (tid < DD) {
        sh_g[tid] = gamma[tid]; sh_b[tid] = beta[tid];
        sh_inv[tid] = -1;
    }
    // W_atom [k][d] -> d-pair packed: float idx = ((d>>1)*33 + k)*2 + (d&1)
    for (int i = tid; i < 32*DD; i += 256) {
        int kk = i >> 7, d = i & 127;
        sh_wt[(((d >> 1)*33) + kk)*2 + (d & 1)] = W_atom[i];
    }
    for (int i = tid; i < 3*DD; i += 256)
        sh_pos[i >> 7][i & 127] = W_pos[i];
    __syncthreads();

    if (tid < 32) sh_inv[sh_allowed[tid]] = tid;    // visible after next sync

    // ---- gather (coalesced float4) ----
    for (int i = tid; i < 32*(DD/4); i += 256) {
        int ia = i >> 5, d4 = i & 31;
        int ga = atom0 + ia;
        int t  = sh_tok[ia];
        float4 qv = ((const float4*)q)[(size_t)ga*(DD/4) + d4];
        float4 av = ((const float4*)g_a2q)[(size_t)(b*NT + t)*(DD/4) + d4];
        *(float4*)&sh_q[ia][d4*4] =
            make_float4(qv.x+av.x, qv.y+av.y, qv.z+av.z, qv.w+av.w);
    }
    __syncthreads();

    // ---- scatter-add, run-length aggregated (tok sorted => ~4 runs/block) ----
    {
        int d    = tid & 127;
        int i0   = (tid >> 7) * 16;
        int cur  = sh_tok[i0];
        float run = 0.f;
#pragma unroll
        for (int i = 0; i < 16; i++) {
            int t = sh_tok[i0 + i];
            if (t != cur) {
                atomicAdd(&g_sfeat[(size_t)(b*NT + cur)*DD + d], run);
                run = 0.f; cur = t;
            }
            run += sh_q[i0 + i][d];
        }
        atomicAdd(&g_sfeat[(size_t)(b*NT + cur)*DD + d], run);
    }

    // ---- atom-type head (FFMA2): thread (ig,k) owns logit k for 4 atoms ----
    const int k   = tid & 31;
    const int ig  = tid >> 5;          // warp id, 0..7
    const int ia0 = ig * 4;
    {
        const unsigned long long* wt2u = (const unsigned long long*)sh_wt;
        unsigned long long ac0 = 0ull, ac1 = 0ull, ac2 = 0ull, ac3 = 0ull;
#pragma unroll 8
        for (int p = 0; p < 64; p += 2) {     // 2 d-pairs = 4 d per iter
            unsigned long long wa = wt2u[p*33 + k];
            unsigned long long wb = wt2u[(p+1)*33 + k];
            int d = p*2;
            ulonglong2 q0 = *(const ulonglong2*)&sh_q[ia0+0][d];  // broadcast
            ulonglong2 q1 = *(const ulonglong2*)&sh_q[ia0+1][d];
            ulonglong2 q2 = *(const ulonglong2*)&sh_q[ia0+2][d];
            ulonglong2 q3 = *(const ulonglong2*)&sh_q[ia0+3][d];
            fma_f32x2(ac0, q0.x, wa); fma_f32x2(ac0, q0.y, wb);
            fma_f32x2(ac1, q1.x, wa); fma_f32x2(ac1, q1.y, wb);
            fma_f32x2(ac2, q2.x, wa); fma_f32x2(ac2, q2.y, wb);
            fma_f32x2(ac3, q3.x, wa); fma_f32x2(ac3, q3.y, wb);
        }
        float bk = sh_batom[k];
        float2 u0 = unpack_f32x2(ac0);
        float2 u1 = unpack_f32x2(ac1);
        float2 u2 = unpack_f32x2(ac2);
        float2 u3 = unpack_f32x2(ac3);
        lg[(ia0+0)*33 + k] = u0.x + u0.y + bk;
        lg[(ia0+1)*33 + k] = u1.x + u1.y + bk;
        lg[(ia0+2)*33 + k] = u2.x + u2.y + bk;
        lg[(ia0+3)*33 + k] = u3.x + u3.y + bk;
    }
    __syncthreads();

    // ---- out_at: direct float4 emit via inverse map ----
    for (int i = tid; i < 32*(DD/4); i += 256) {
        int ia = i >> 5, d4 = i & 31;
        int c0 = d4 * 4;
        int k0 = sh_inv[c0+0], k1 = sh_inv[c0+1];
        int k2 = sh_inv[c0+2], k3 = sh_inv[c0+3];
        float4 v;
        v.x = (k0 >= 0) ? lg[ia*33 + k0] : PAD_VALF;
        v.y = (k1 >= 0) ? lg[ia*33 + k1] : PAD_VALF;
        v.z = (k2 >= 0) ? lg[ia*33 + k2] : PAD_VALF;
        v.w = (k3 >= 0) ? lg[ia*33 + k3] : PAD_VALF;
        ((float4*)out_at)[(size_t)(atom0 + ia)*(DD/4) + d4] = v;
    }

    // ---- LayerNorm + pos head: warp ig handles atoms ia0..ia0+3 ----
    const int lane  = k;
    const int dbase = lane * 4;
    for (int r = 0; r < 4; r++) {
        int ia = ia0 + r;
        float4 v = *(const float4*)&sh_q[ia][dbase];
        float s = v.x + v.y + v.z + v.w;
#pragma unroll
        for (int o = 16; o > 0; o >>= 1) s += __shfl_xor_sync(0xffffffffu, s, o);
        float mu = s * (1.f/128.f);
        float d0 = v.x-mu, d1 = v.y-mu, d2 = v.z-mu, d3 = v.w-mu;
        float sq = d0*d0 + d1*d1 + d2*d2 + d3*d3;
#pragma unroll
        for (int o = 16; o > 0; o >>= 1) sq += __shfl_xor_sync(0xffffffffu, sq, o);
        float inv = rsqrtf(sq * (1.f/128.f) + 1e-5f);
        float n0 = d0*inv*sh_g[dbase+0] + sh_b[dbase+0];
        float n1 = d1*inv*sh_g[dbase+1] + sh_b[dbase+1];
        float n2 = d2*inv*sh_g[dbase+2] + sh_b[dbase+2];
        float n3 = d3*inv*sh_g[dbase+3] + sh_b[dbase+3];
        float p0 = n0*sh_pos[0][dbase+0] + n1*sh_pos[0][dbase+1]
                 + n2*sh_pos[0][dbase+2] + n3*sh_pos[0][dbase+3];
        float p1 = n0*sh_pos[1][dbase+0] + n1*sh_pos[1][dbase+1]
                 + n2*sh_pos[1][dbase+2] + n3*sh_pos[1][dbase+3];
        float p2 = n0*sh_pos[2][dbase+0] + n1*sh_pos[2][dbase+1]
                 + n2*sh_pos[2][dbase+2] + n3*sh_pos[2][dbase+3];
#pragma unroll
        for (int o = 16; o > 0; o >>= 1) {
            p0 += __shfl_xor_sync(0xffffffffu, p0, o);
            p1 += __shfl_xor_sync(0xffffffffu, p1, o);
            p2 += __shfl_xor_sync(0xffffffffu, p2, o);
        }
        if (lane == 0) {
            size_t ro = (size_t)(atom0 + ia) * 3;
            out_r[ro+0] = p0; out_r[ro+1] = p1; out_r[ro+2] = p2;
        }
    }
}

// ---------------------------------------------------------------------------
// k3: res_type[bt,k] = s_feat[bt,:] . W_res[k,:] + b_res[k]   (FFMA2)
// 256 blocks x 256 threads; 16 tokens/block; warp = 2 tokens, lane = k.
// ---------------------------------------------------------------------------
__global__ void __launch_bounds__(256) k3_res(const float* __restrict__ W_res,
                                              const float* __restrict__ b_res,
                                              float* __restrict__ out_res)
{
    __shared__ __align__(16) float shW[33*132];    // 17.4 KB: [k][132]
    __shared__ __align__(16) float shF[16*DD];     // 8 KB

    const int tid = threadIdx.x;
    const int bt0 = blockIdx.x * 16;

    for (int i = tid; i < 33*DD; i += 256)          // i = k*128 + d
        shW[(i >> 7)*132 + (i & 127)] = W_res[i];
    {
        const float4* src = (const float4*)(g_sfeat + (size_t)bt0*DD);
        ((float4*)shF)[tid]       = src[tid];
        ((float4*)shF)[tid + 256] = src[tid + 256];
    }
    __syncthreads();

    const int lane = tid & 31;                      // k
    const int w    = tid >> 5;                      // 0..7
    const int t0   = w * 2;
    const float* f0p = &shF[t0*DD];
    const float* f1p = &shF[(t0+1)*DD];

    unsigned long long a0p = 0ull, a1p = 0ull;
#pragma unroll 16
    for (int d = 0; d < DD; d += 4) {
        ulonglong2 wu  = *(const ulonglong2*)&shW[lane*132 + d];
        ulonglong2 f0u = *(const ulonglong2*)(f0p + d);   // broadcast
        ulonglong2 f1u = *(const ulonglong2*)(f1p + d);
        fma_f32x2(a0p, f0u.x, wu.x); fma_f32x2(a0p, f0u.y, wu.y);
        fma_f32x2(a1p, f1u.x, wu.x); fma_f32x2(a1p, f1u.y, wu.y);
    }
    {
        float bk = b_res[lane];
        float2 u0 = unpack_f32x2(a0p);
        float2 u1 = unpack_f32x2(a1p);
        out_res[(size_t)(bt0 + t0)*33 + lane]     = u0.x + u0.y + bk;
        out_res[(size_t)(bt0 + t0 + 1)*33 + lane] = u1.x + u1.y + bk;
    }

    // k = 32: lane-parallel partial dots + shuffle reduce (both tokens)
    {
        const int dbase = lane * 4;
        float4 wv = *(const float4*)&shW[32*132 + dbase];
        float4 a0 = *(const float4*)(f0p + dbase);
        float4 a1 = *(const float4*)(f1p + dbase);
        float s0 = a0.x*wv.x + a0.y*wv.y + a0.z*wv.z + a0.w*wv.w;
        float s1 = a1.x*wv.x + a1.y*wv.y + a1.z*wv.z + a1.w*wv.w;
#pragma unroll
        for (int o = 16; o > 0; o >>= 1) {
            s0 += __shfl_xor_sync(0xffffffffu, s0, o);
            s1 += __shfl_xor_sync(0xffffffffu, s1, o);
        }
        if (lane == 0) {
            float b32 = b_res[32];
            out_res[(size_t)(bt0 + t0)*33 + 32]     = s0 + b32;
            out_res[(size_t)(bt0 + t0 + 1)*33 + 32] = s1 + b32;
        }
    }
}

// ---------------------------------------------------------------------------
extern "C" void kernel_launch(void* const* d_in, const int* in_sizes, int n_in,
                              void* d_out, int out_size)
{
    const float* a      = (const float*)d_in[0];
    const float* q      = (const float*)d_in[1];
    // d_in[2] = c            (unused by reference)
    const int*   tok    = (const int*)  d_in[3];
    // d_in[4] = atom_to_token one-hot (replaced by gather via tok)
    // d_in[5] = atom_pad_mask (all ones by construction)
    const float* W_a2q  = (const float*)d_in[6];
    const float* gamma  = (const float*)d_in[7];
    const float* beta   = (const float*)d_in[8];
    const float* W_pos  = (const float*)d_in[9];
    const float* W_res  = (const float*)d_in[10];
    const float* b_res  = (const float*)d_in[11];
    const float* W_atom = (const float*)d_in[12];
    const float* b_atom = (const float*)d_in[13];
    const int*   allowed= (const int*)  d_in[14];

    float* out     = (float*)d_out;
    float* out_r   = out;                                   // [B,NA,3]
    float* out_res = out + (size_t)BB*NA*3;                 // [B,NT,33]
    float* out_at  = out_res + (size_t)BB*NT*33;            // [B,NA,128]

    k1_gemm <<<BT_TOT/16, 256>>>(a, W_a2q);
    k2_atoms<<<GA_TOT/32, 256>>>(q, tok, W_atom, b_atom, allowed,
                                 gamma, beta, W_pos, out_r, out_at);
    k3_res  <<<BT_TOT/16, 256>>>(W_res, b_res, out_res);
}